// round 11
// baseline (speedup 1.0000x reference)
#include <cuda_runtime.h>
#include <math.h>

#define DINL __device__ __forceinline__
DINL float sigf(float x){ return 1.f/(1.f+expf(-x)); }

// ---------------- device scratch ----------------
__device__ float g_pre [(size_t)64*1024*2048];
__device__ float g_buf0[(size_t)64*1024*512];
__device__ float g_buf1[(size_t)64*512*512];
__device__ float g_feats[(size_t)64*256*512];
__device__ float g_cf  [(size_t)64*256*128];
__device__ float g_hA[2*64*256];          // h double-buffer, parity 0
__device__ float g_hB[2*64*256];          // parity 1
__device__ float g_c [2*64*256];          // final cell state (layer outputs)
__device__ float g_tokpre[(size_t)150*64*2048];
__device__ float g_Wcat[(size_t)2048*1024];
__device__ float g_dxA[64*1024];
__device__ float g_dxB[64*1024];
__device__ unsigned g_bar[8];             // global barrier counters (reset each replay)

// ---------------- global barrier (all blocks co-resident, counter monotonic) ----
DINL void gbar(unsigned* bar, unsigned target){
  __syncthreads();
  if (threadIdx.x == 0){
    __threadfence();
    atomicAdd(bar, 1u);
    volatile unsigned* vb = (volatile unsigned*)bar;
    while (*vb < target) __nanosleep(64);
    __threadfence();
  }
  __syncthreads();
}

// ---------------- generic SGEMM: C[M,N] = A[M,K] @ W[N,K]^T + bias ----------------
__global__ void __launch_bounds__(256) sgemm_k(
    const float* __restrict__ A, const float* __restrict__ W,
    const float* __restrict__ bias, float* __restrict__ C,
    int K, int ldc, int relu)
{
  __shared__ __align__(16) float As[8][128];
  __shared__ __align__(16) float Bs[8][128];
  const int tid = threadIdx.x;
  const int tx = tid & 15, ty = tid >> 4;
  const size_t rA0 = (size_t)blockIdx.y * 128;
  const int    rW0 = blockIdx.x * 128;
  const float* Ag = A + rA0 * K;
  const float* Wg = W + (size_t)rW0 * K;
  const int lr = tid >> 1, lc = (tid & 1) * 4;

  float acc[8][8];
#pragma unroll
  for (int i=0;i<8;i++)
#pragma unroll
    for (int j=0;j<8;j++) acc[i][j] = 0.f;

  for (int k0 = 0; k0 < K; k0 += 8) {
    float4 av = *(const float4*)(Ag + (size_t)lr*K + k0 + lc);
    float4 wv = *(const float4*)(Wg + (size_t)lr*K + k0 + lc);
    As[lc+0][lr]=av.x; As[lc+1][lr]=av.y; As[lc+2][lr]=av.z; As[lc+3][lr]=av.w;
    Bs[lc+0][lr]=wv.x; Bs[lc+1][lr]=wv.y; Bs[lc+2][lr]=wv.z; Bs[lc+3][lr]=wv.w;
    __syncthreads();
#pragma unroll
    for (int k=0;k<8;k++){
      float a[8], b[8];
      *(float4*)&a[0] = *(const float4*)&As[k][ty*8];
      *(float4*)&a[4] = *(const float4*)&As[k][ty*8+4];
      *(float4*)&b[0] = *(const float4*)&Bs[k][tx*8];
      *(float4*)&b[4] = *(const float4*)&Bs[k][tx*8+4];
#pragma unroll
      for (int i=0;i<8;i++)
#pragma unroll
        for (int j=0;j<8;j++) acc[i][j] = fmaf(a[i], b[j], acc[i][j]);
    }
    __syncthreads();
  }

  float bb[8];
#pragma unroll
  for (int j=0;j<8;j++) bb[j] = bias[rW0 + tx*8 + j];
#pragma unroll
  for (int i=0;i<8;i++){
    size_t r = rA0 + ty*8 + i;
    float* cp = C + r*(size_t)ldc + rW0 + tx*8;
    float v[8];
#pragma unroll
    for (int j=0;j<8;j++){
      v[j] = acc[i][j] + bb[j];
      if (relu) v[j] = fmaxf(v[j], 0.f);
    }
    *(float4*)cp     = *(float4*)&v[0];
    *(float4*)(cp+4) = *(float4*)&v[4];
  }
}

// ---------------- persistent encoder biLSTM scan (one launch per layer) ----------
// grid (16 utiles, 4 btiles, 2 dirs) = 128 blocks, 256 threads.
// Thread owns one (b,u) cell; c stays in a register across all T steps.
__global__ void __launch_bounds__(256) enc_scan_k(
    const float* __restrict__ Whh_f, const float* __restrict__ Whh_b,
    float* __restrict__ outbuf, int T, unsigned* bar)
{
  const int dir = blockIdx.z;
  const int u0 = blockIdx.x * 16;
  const int b0 = blockIdx.y * 16;
  const float* __restrict__ Whh = dir ? Whh_b : Whh_f;
  const int tid = threadIdx.x;
  const int tb = tid >> 4, tu = tid & 15;
  const int b = b0 + tb, u = u0 + tu;
  const int hoff = dir*16384 + b*256 + u;

  __shared__ float hs[16][65];
  __shared__ float ws[4][64][17];

  // zero initial h (parity-0 buffer), c in register
  g_hA[hoff] = 0.f;
  float c_reg = 0.f;
  __threadfence();
  gbar(bar, 128u);

  for (int s = 0; s < T; s++){
    const int t = dir ? (T-1-s) : s;
    const float* __restrict__ h_in = ((s&1) ? g_hB : g_hA) + dir*16384;
    float* __restrict__ h_out      =  (s&1) ? g_hA : g_hB;
    float a0=0.f, a1=0.f, a2=0.f, a3=0.f;

    for (int kc = 0; kc < 256; kc += 64) {
      {
        int r = tid >> 4, c4 = (tid & 15) * 4;
        float4 v = __ldcg((const float4*)(h_in + (b0 + r)*256 + kc + c4));
        hs[r][c4]=v.x; hs[r][c4+1]=v.y; hs[r][c4+2]=v.z; hs[r][c4+3]=v.w;
      }
#pragma unroll
      for (int l = 0; l < 4; l++) {
        int l4 = tid + l*256;
        int gate = l4 >> 8, unit = (l4 >> 4) & 15, kq = (l4 & 15) * 4;
        float4 v = *(const float4*)(Whh + (size_t)(gate*256 + u0 + unit)*256 + kc + kq);
        ws[gate][kq+0][unit]=v.x; ws[gate][kq+1][unit]=v.y;
        ws[gate][kq+2][unit]=v.z; ws[gate][kq+3][unit]=v.w;
      }
      __syncthreads();
#pragma unroll 8
      for (int k=0;k<64;k++){
        float hv = hs[tb][k];
        a0 = fmaf(hv, ws[0][k][tu], a0);
        a1 = fmaf(hv, ws[1][k][tu], a1);
        a2 = fmaf(hv, ws[2][k][tu], a2);
        a3 = fmaf(hv, ws[3][k][tu], a3);
      }
      __syncthreads();
    }
    const float* pz = g_pre + ((size_t)b*T + t)*2048 + dir*1024 + u;
    float zi = a0 + pz[0];
    float zf = a1 + pz[256];
    float zg = a2 + pz[512];
    float zo = a3 + pz[768];
    c_reg = sigf(zf)*c_reg + sigf(zi)*tanhf(zg);
    float hn = sigf(zo)*tanhf(c_reg);
    h_out[hoff] = hn;
    outbuf[((size_t)b*T + t)*512 + dir*256 + u] = hn;
    __threadfence();
    gbar(bar, 128u*(unsigned)(s+2));
  }
  g_c[hoff] = c_reg;   // final c (used by write_hc for layer 2; T even -> final h in g_hA)
}

// ---------------- persistent decoder: 150 x (cell -> attn) in one launch ----------
// 128 blocks, 256 threads. Cell mapping: u0=(bid&31)*16, b0=(bid>>5)*16.
// Attn phase: blocks 0..63, one per batch.
__global__ void __launch_bounds__(256) dec_scan_k(
    const float* __restrict__ phi_W, const float* __restrict__ phi_b,
    const float* __restrict__ fc_W, const float* __restrict__ fc_b,
    float* __restrict__ out, unsigned* bar)
{
  const int bid = blockIdx.x;
  const int tid = threadIdx.x;
  const int u0 = (bid & 31) * 16;
  const int b0 = (bid >> 5) * 16;
  const int tb = tid >> 4, tu = tid & 15;

  __shared__ float xs[16][65];
  __shared__ float ws[4][64][17];
  __shared__ __align__(16) float sh[512], sq[128], satt[256], sctx[512], slog[48];
  __shared__ float sred[8];

  float c_reg = 0.f;

  for (int s = 0; s < 150; s++){
    const float* __restrict__ dx_in = (s&1) ? g_dxB : g_dxA;
    float* __restrict__ dx_out      = (s&1) ? g_dxA : g_dxB;

    // ---- LSTM cell: z = [ctx|h] @ Wcat^T (+ tokpre), K=1024 ----
    float a0=0.f, a1=0.f, a2=0.f, a3=0.f;
    for (int kc = 0; kc < 1024; kc += 64) {
      {
        int r = tid >> 4, c4 = (tid & 15) * 4;
        float4 v = __ldcg((const float4*)(dx_in + (b0 + r)*1024 + kc + c4));
        xs[r][c4]=v.x; xs[r][c4+1]=v.y; xs[r][c4+2]=v.z; xs[r][c4+3]=v.w;
      }
#pragma unroll
      for (int l = 0; l < 4; l++) {
        int l4 = tid + l*256;
        int gate = l4 >> 8, unit = (l4 >> 4) & 15, kq = (l4 & 15) * 4;
        float4 v = *(const float4*)(g_Wcat + (size_t)(gate*512 + u0 + unit)*1024 + kc + kq);
        ws[gate][kq+0][unit]=v.x; ws[gate][kq+1][unit]=v.y;
        ws[gate][kq+2][unit]=v.z; ws[gate][kq+3][unit]=v.w;
      }
      __syncthreads();
#pragma unroll 8
      for (int k=0;k<64;k++){
        float xv = xs[tb][k];
        a0 = fmaf(xv, ws[0][k][tu], a0);
        a1 = fmaf(xv, ws[1][k][tu], a1);
        a2 = fmaf(xv, ws[2][k][tu], a2);
        a3 = fmaf(xv, ws[3][k][tu], a3);
      }
      __syncthreads();
    }
    {
      const int b = b0 + tb, u = u0 + tu;
      const float* tp = g_tokpre + ((size_t)s*64 + b)*2048;
      float zi = a0 + tp[u];
      float zf = a1 + tp[512 + u];
      float zg = a2 + tp[1024 + u];
      float zo = a3 + tp[1536 + u];
      c_reg = sigf(zf)*c_reg + sigf(zi)*tanhf(zg);
      dx_out[b*1024 + 512 + u] = sigf(zo)*tanhf(c_reg);
    }
    __threadfence();
    gbar(bar, 128u*(unsigned)(2*s+1));

    // ---- attention + context + logits + log_softmax (blocks 0..63) ----
    if (bid < 64) {
      const int b = bid;
      float* dxb = dx_out + b*1024;
      sh[tid]       = __ldcg(&dxb[512 + tid]);
      sh[tid + 256] = __ldcg(&dxb[768 + tid]);
      __syncthreads();

      // q = relu(h @ phi_W^T + phi_b)
      {
        int m = tid & 127, half = tid >> 7;
        const float* w = phi_W + (size_t)m*512 + half*256;
        float acc = 0.f;
        for (int k=0;k<256;k+=4){
          float4 hv = *(float4*)&sh[half*256 + k];
          float4 wv = *(const float4*)&w[k];
          acc += hv.x*wv.x + hv.y*wv.y + hv.z*wv.z + hv.w*wv.w;
        }
        if (half == 0) sq[m] = acc;
        __syncthreads();
        if (half == 1) sq[m] = fmaxf(sq[m] + acc + phi_b[m], 0.f);
        __syncthreads();
      }

      // scores + softmax over t
      {
        const float* cfp = g_cf + ((size_t)b*256 + tid)*128;
        float sc = 0.f;
        for (int m=0;m<128;m+=4){
          float4 qv = *(float4*)&sq[m];
          float4 cv = *(const float4*)&cfp[m];
          sc += qv.x*cv.x + qv.y*cv.y + qv.z*cv.z + qv.w*cv.w;
        }
        float mx = sc;
        for (int o=16;o;o>>=1) mx = fmaxf(mx, __shfl_xor_sync(~0u, mx, o));
        if ((tid & 31) == 0) sred[tid>>5] = mx;
        __syncthreads();
        float bm = sred[0];
#pragma unroll
        for (int i=1;i<8;i++) bm = fmaxf(bm, sred[i]);
        float e = expf(sc - bm);
        float sm = e;
        for (int o=16;o;o>>=1) sm += __shfl_xor_sync(~0u, sm, o);
        __syncthreads();
        if ((tid & 31) == 0) sred[tid>>5] = sm;
        __syncthreads();
        float ts = 0.f;
#pragma unroll
        for (int i=0;i<8;i++) ts += sred[i];
        satt[tid] = e / ts;
        __syncthreads();
      }

      // ctx = att @ feats[b]
      {
        const float* fb = g_feats + (size_t)b*256*512;
        float a4=0.f, a5=0.f;
        for (int t=0;t<256;t++){
          float at = satt[t];
          const float* fr = fb + (size_t)t*512;
          a4 = fmaf(at, fr[tid],       a4);
          a5 = fmaf(at, fr[tid + 256], a5);
        }
        sctx[tid] = a4; sctx[tid+256] = a5;
        dxb[tid] = a4;  dxb[tid+256] = a5;
        __syncthreads();
      }

      // logits + log_softmax
      if (tid < 48) {
        const float* w = fc_W + (size_t)tid*1024;
        float acc = fc_b[tid];
        for (int k=0;k<512;k+=4){
          float4 hv = *(float4*)&sh[k];
          float4 w1 = *(const float4*)&w[k];
          acc += hv.x*w1.x + hv.y*w1.y + hv.z*w1.z + hv.w*w1.w;
          float4 cv = *(float4*)&sctx[k];
          float4 w2 = *(const float4*)&w[512 + k];
          acc += cv.x*w2.x + cv.y*w2.y + cv.z*w2.z + cv.w*w2.w;
        }
        slog[tid] = acc;
      }
      __syncthreads();
      if (tid == 0) {
        float mx = slog[0];
        for (int i=1;i<48;i++) mx = fmaxf(mx, slog[i]);
        float sm = 0.f;
        for (int i=0;i<48;i++) sm += expf(slog[i] - mx);
        sred[0] = mx + logf(sm);
      }
      __syncthreads();
      if (tid < 48) out[((size_t)b*150 + s)*48 + tid] = slog[tid] - sred[0];
      __syncthreads();
    }
    __threadfence();
    gbar(bar, 128u*(unsigned)(2*s+2));
  }
}

// ---------------- small prep/util kernels ----------------
__global__ void zero_bar_k(){
  if (threadIdx.x < 8) g_bar[threadIdx.x] = 0u;
}
__global__ void prep_wcat_k(const float* __restrict__ s_Wih, const float* __restrict__ s_Whh){
  size_t i = (size_t)blockIdx.x*256 + threadIdx.x;     // 2048*1024
  int j = (int)(i & 1023), g = (int)(i >> 10);
  g_Wcat[i] = (j < 512) ? s_Wih[(size_t)g*560 + 48 + j]
                        : s_Whh[(size_t)g*512 + j - 512];
}
__global__ void prep_tok_k(const int* __restrict__ gt,
                           const float* __restrict__ s_Wih,
                           const float* __restrict__ s_b){
  size_t i = (size_t)blockIdx.x*256 + threadIdx.x;     // 150*64*2048
  int g = (int)(i & 2047);
  int sb = (int)(i >> 11);
  int b = sb & 63, s = sb >> 6;
  int tok = (s == 0) ? 0 : gt[b*150 + s - 1];
  g_tokpre[i] = s_b[g] + s_Wih[(size_t)g*560 + tok];
}
__global__ void dec_init_k(){
  int i = blockIdx.x*256 + threadIdx.x;                // 64*1024
  int b = i >> 10, j = i & 1023;
  g_dxA[i] = (j < 512) ? g_feats[(size_t)b*256*512 + j] : 0.f;
}
__global__ void write_hc_k(float* __restrict__ out){
  int i = blockIdx.x*256 + threadIdx.x;                // 64*1024
  int b = i >> 10, j = i & 1023;
  int dir = (j >> 8) & 1, u = j & 255;
  float v = (j < 512) ? g_hA[dir*16384 + b*256 + u]
                      : g_c [dir*16384 + b*256 + u];
  out[i] = v;
}

// ---------------- launch ----------------
extern "C" void kernel_launch(void* const* d_in, const int* in_sizes, int n_in,
                              void* d_out, int out_size)
{
  (void)in_sizes; (void)n_in; (void)out_size;
  const float* inputs = (const float*)d_in[0];
  const int*   gt     = (const int*)d_in[1];
  const float* P[29];
  for (int i=2;i<29;i++) P[i] = (const float*)d_in[i];
  float* out = (float*)d_out;

  float *pre, *buf0, *buf1, *feats, *cfb;
  unsigned* dbar;
  cudaGetSymbolAddress((void**)&pre,   g_pre);
  cudaGetSymbolAddress((void**)&buf0,  g_buf0);
  cudaGetSymbolAddress((void**)&buf1,  g_buf1);
  cudaGetSymbolAddress((void**)&feats, g_feats);
  cudaGetSymbolAddress((void**)&cfb,   g_cf);
  cudaGetSymbolAddress((void**)&dbar,  g_bar);

  zero_bar_k<<<1, 32>>>();

  // ---- encoder: 3 pyramid biLSTM layers ----
  const float* Xs[3] = { inputs, buf0, buf1 };
  float*       Os[3] = { buf0, buf1, feats };
  const int    Ks[3] = { 160, 1024, 1024 };
  const int    Ts[3] = { 1024, 512, 256 };

  for (int l = 0; l < 3; l++) {
    const int base = 2 + l*6;
    const int M = 64 * Ts[l];
    sgemm_k<<<dim3(8, M/128), 256>>>(Xs[l], P[base+0], P[base+2], pre,        Ks[l], 2048, 0);
    sgemm_k<<<dim3(8, M/128), 256>>>(Xs[l], P[base+3], P[base+5], pre + 1024, Ks[l], 2048, 0);
    enc_scan_k<<<dim3(16,4,2), 256>>>(P[base+1], P[base+4], Os[l], Ts[l], dbar + l);
  }

  // ---- comp_feat = relu(feats @ psi_W^T + psi_b) ----
  sgemm_k<<<dim3(1, 128), 256>>>(feats, P[25], P[26], cfb, 512, 128, 1);

  // ---- decoder prep ----
  prep_wcat_k<<<8192, 256>>>(P[20], P[21]);
  prep_tok_k<<<76800, 256>>>(gt, P[20], P[22]);
  dec_init_k<<<256, 256>>>();

  // ---- decoder (persistent, all 150 steps) ----
  dec_scan_k<<<128, 256>>>(P[23], P[24], P[27], P[28], out, dbar + 3);

  // ---- listener_hc ----
  write_hc_k<<<256, 256>>>(out + (size_t)64*150*48);
}

// round 14
// speedup vs baseline: 1.4774x; 1.4774x over previous
#include <cuda_runtime.h>
#include <math.h>

#define DINL __device__ __forceinline__
DINL float sigf(float x){ return 1.f/(1.f+expf(-x)); }

// ---------------- device scratch ----------------
__device__ float g_pre [(size_t)64*1024*2048];
__device__ float g_buf0[(size_t)64*1024*512];
__device__ float g_buf1[(size_t)64*512*512];
__device__ float g_feats[(size_t)64*256*512];
__device__ float g_cf  [(size_t)64*256*128];
__device__ float g_hA[2*64*256];          // h double-buffer, parity 0
__device__ float g_hB[2*64*256];          // parity 1
__device__ float g_c [2*64*256];          // final cell state (layer outputs)
__device__ float g_tokpre[(size_t)150*64*2048];
__device__ float g_Wcat[(size_t)2048*1024];
__device__ float g_dxA[64*1024];
__device__ float g_dxB[64*1024];
__device__ unsigned g_bar[8];             // global barrier counters (reset each replay)

// ---------------- global barrier (all blocks co-resident, counter monotonic) ----
DINL void gbar(unsigned* bar, unsigned target){
  __syncthreads();
  if (threadIdx.x == 0){
    __threadfence();
    atomicAdd(bar, 1u);
    volatile unsigned* vb = (volatile unsigned*)bar;
    while (*vb < target) { }
    __threadfence();
  }
  __syncthreads();
}

// ---------------- generic SGEMM: C[M,N] = A[M,K] @ W[N,K]^T + bias ----------------
__global__ void __launch_bounds__(256) sgemm_k(
    const float* __restrict__ A, const float* __restrict__ W,
    const float* __restrict__ bias, float* __restrict__ C,
    int K, int ldc, int relu)
{
  __shared__ __align__(16) float As[8][128];
  __shared__ __align__(16) float Bs[8][128];
  const int tid = threadIdx.x;
  const int tx = tid & 15, ty = tid >> 4;
  const size_t rA0 = (size_t)blockIdx.y * 128;
  const int    rW0 = blockIdx.x * 128;
  const float* Ag = A + rA0 * K;
  const float* Wg = W + (size_t)rW0 * K;
  const int lr = tid >> 1, lc = (tid & 1) * 4;

  float acc[8][8];
#pragma unroll
  for (int i=0;i<8;i++)
#pragma unroll
    for (int j=0;j<8;j++) acc[i][j] = 0.f;

  for (int k0 = 0; k0 < K; k0 += 8) {
    float4 av = *(const float4*)(Ag + (size_t)lr*K + k0 + lc);
    float4 wv = *(const float4*)(Wg + (size_t)lr*K + k0 + lc);
    As[lc+0][lr]=av.x; As[lc+1][lr]=av.y; As[lc+2][lr]=av.z; As[lc+3][lr]=av.w;
    Bs[lc+0][lr]=wv.x; Bs[lc+1][lr]=wv.y; Bs[lc+2][lr]=wv.z; Bs[lc+3][lr]=wv.w;
    __syncthreads();
#pragma unroll
    for (int k=0;k<8;k++){
      float a[8], b[8];
      *(float4*)&a[0] = *(const float4*)&As[k][ty*8];
      *(float4*)&a[4] = *(const float4*)&As[k][ty*8+4];
      *(float4*)&b[0] = *(const float4*)&Bs[k][tx*8];
      *(float4*)&b[4] = *(const float4*)&Bs[k][tx*8+4];
#pragma unroll
      for (int i=0;i<8;i++)
#pragma unroll
        for (int j=0;j<8;j++) acc[i][j] = fmaf(a[i], b[j], acc[i][j]);
    }
    __syncthreads();
  }

  float bb[8];
#pragma unroll
  for (int j=0;j<8;j++) bb[j] = bias[rW0 + tx*8 + j];
#pragma unroll
  for (int i=0;i<8;i++){
    size_t r = rA0 + ty*8 + i;
    float* cp = C + r*(size_t)ldc + rW0 + tx*8;
    float v[8];
#pragma unroll
    for (int j=0;j<8;j++){
      v[j] = acc[i][j] + bb[j];
      if (relu) v[j] = fmaxf(v[j], 0.f);
    }
    *(float4*)cp     = *(float4*)&v[0];
    *(float4*)(cp+4) = *(float4*)&v[4];
  }
}

// ---------------- persistent encoder biLSTM scan (one launch per layer) ----------
// grid (16 utiles, 4 btiles, 2 dirs) = 128 blocks, 256 threads.
// Whh slice (4 gates x 16 units x 256 k = 64KB) resident in dynamic smem.
// Accum phase: thread = (gu = gate*16+ui, batch-quad). Gate phase: thread = (b,u),
// c kept in a register across all T steps.
__global__ void __launch_bounds__(256) enc_scan_k(
    const float* __restrict__ Whh_f, const float* __restrict__ Whh_b,
    float* __restrict__ outbuf, int T, unsigned* bar)
{
  extern __shared__ float sm[];
  float* ws = sm;                 // [256][64]  ws[k*64+gu]
  float* hs = sm + 256*64;        // [16][256]  hs[b*256+k]
  float* zb = hs + 16*256;        // [64][17]   zb[gu*17+b]

  const int dir = blockIdx.z;
  const int u0 = blockIdx.x * 16;
  const int b0 = blockIdx.y * 16;
  const float* __restrict__ Whh = dir ? Whh_b : Whh_f;
  const int tid = threadIdx.x;

  const int gu = tid & 63;        // accum-phase id: gate*16+ui
  const int bq = (tid >> 6) * 4;  // batch quad base 0/4/8/12
  const int uu = tid & 15, bb = tid >> 4;   // gate-phase id
  const int hoff = dir*16384 + (b0+bb)*256 + u0 + uu;

  // ---- load Whh slice to smem (once) ----
  {
    const int g = gu >> 4, ui = gu & 15;
    const float* wrow = Whh + (size_t)(g*256 + u0 + ui) * 256;
    const int kq0 = tid >> 6;
#pragma unroll
    for (int i = 0; i < 16; i++) {
      int k4 = kq0 + i*4;                 // float4 index along k (0..63)
      float4 v = *(const float4*)(wrow + k4*4);
      ws[(k4*4+0)*64 + gu] = v.x;
      ws[(k4*4+1)*64 + gu] = v.y;
      ws[(k4*4+2)*64 + gu] = v.z;
      ws[(k4*4+3)*64 + gu] = v.w;
    }
  }

  // ---- init h=0 (parity-0 buffer), c in register ----
  g_hA[hoff] = 0.f;
  float c_reg = 0.f;
  __threadfence();
  gbar(bar, 128u);

  for (int s = 0; s < T; s++){
    const int t = dir ? (T-1-s) : s;
    const float* __restrict__ h_in = ((s&1) ? g_hB : g_hA) + dir*16384 + b0*256;
    float* __restrict__ h_out      =  (s&1) ? g_hA : g_hB;

    // stage h tile [16][256] (coalesced float4)
#pragma unroll
    for (int i = 0; i < 4; i++){
      int idx = tid + i*256;
      float4 v = __ldcg((const float4*)h_in + idx);
      *((float4*)hs + idx) = v;
    }
    // prefetch pre-activation gates for this (b,u,t)
    const float* pz = g_pre + ((size_t)(b0+bb)*T + t)*2048 + dir*1024 + u0 + uu;
    float p0 = __ldg(pz);
    float p1 = __ldg(pz + 256);
    float p2 = __ldg(pz + 512);
    float p3 = __ldg(pz + 768);
    __syncthreads();

    // accum: 4 batches x 1 gate-unit per thread, k in quads
    float a0=0.f, a1=0.f, a2=0.f, a3=0.f;
    const float* hp0 = hs + (bq+0)*256;
    const float* hp1 = hs + (bq+1)*256;
    const float* hp2 = hs + (bq+2)*256;
    const float* hp3 = hs + (bq+3)*256;
    const float* wp  = ws + gu;
#pragma unroll 2
    for (int k = 0; k < 256; k += 4){
      float4 h0 = *(const float4*)(hp0 + k);
      float4 h1 = *(const float4*)(hp1 + k);
      float4 h2 = *(const float4*)(hp2 + k);
      float4 h3 = *(const float4*)(hp3 + k);
      float w0 = wp[(k+0)*64];
      float w1 = wp[(k+1)*64];
      float w2 = wp[(k+2)*64];
      float w3 = wp[(k+3)*64];
      a0 = fmaf(h0.x,w0,a0); a1 = fmaf(h1.x,w0,a1); a2 = fmaf(h2.x,w0,a2); a3 = fmaf(h3.x,w0,a3);
      a0 = fmaf(h0.y,w1,a0); a1 = fmaf(h1.y,w1,a1); a2 = fmaf(h2.y,w1,a2); a3 = fmaf(h3.y,w1,a3);
      a0 = fmaf(h0.z,w2,a0); a1 = fmaf(h1.z,w2,a1); a2 = fmaf(h2.z,w2,a2); a3 = fmaf(h3.z,w2,a3);
      a0 = fmaf(h0.w,w3,a0); a1 = fmaf(h1.w,w3,a1); a2 = fmaf(h2.w,w3,a2); a3 = fmaf(h3.w,w3,a3);
    }
    // exchange z to (b,u) owners
    zb[gu*17 + bq+0] = a0;
    zb[gu*17 + bq+1] = a1;
    zb[gu*17 + bq+2] = a2;
    zb[gu*17 + bq+3] = a3;
    __syncthreads();

    // gate math on (bb,uu)
    float zi = zb[(     uu)*17 + bb] + p0;
    float zf = zb[(16 + uu)*17 + bb] + p1;
    float zg = zb[(32 + uu)*17 + bb] + p2;
    float zo = zb[(48 + uu)*17 + bb] + p3;
    c_reg = sigf(zf)*c_reg + sigf(zi)*tanhf(zg);
    float hn = sigf(zo)*tanhf(c_reg);
    h_out[hoff] = hn;
    outbuf[((size_t)(b0+bb)*T + t)*512 + dir*256 + u0 + uu] = hn;
    __threadfence();
    gbar(bar, 128u*(unsigned)(s+2));
  }
  g_c[hoff] = c_reg;   // final c; T even -> final h ended in g_hA
}

// ---------------- persistent decoder: 150 x (cell -> attn) in one launch ----------
__global__ void __launch_bounds__(256) dec_scan_k(
    const float* __restrict__ phi_W, const float* __restrict__ phi_b,
    const float* __restrict__ fc_W, const float* __restrict__ fc_b,
    float* __restrict__ out, unsigned* bar)
{
  const int bid = blockIdx.x;
  const int tid = threadIdx.x;
  const int u0 = (bid & 31) * 16;
  const int b0 = (bid >> 5) * 16;
  const int tb = tid >> 4, tu = tid & 15;

  __shared__ float xs[16][65];
  __shared__ float wsl[4][64][17];
  __shared__ __align__(16) float sh[512], sq[128], satt[256], sctx[512], slog[48];
  __shared__ float sred[8];

  float c_reg = 0.f;

  for (int s = 0; s < 150; s++){
    const float* __restrict__ dx_in = (s&1) ? g_dxB : g_dxA;
    float* __restrict__ dx_out      = (s&1) ? g_dxA : g_dxB;

    // ---- LSTM cell: z = [ctx|h] @ Wcat^T (+ tokpre), K=1024 ----
    float a0=0.f, a1=0.f, a2=0.f, a3=0.f;
    for (int kc = 0; kc < 1024; kc += 64) {
      {
        int r = tid >> 4, c4 = (tid & 15) * 4;
        float4 v = __ldcg((const float4*)(dx_in + (b0 + r)*1024 + kc + c4));
        xs[r][c4]=v.x; xs[r][c4+1]=v.y; xs[r][c4+2]=v.z; xs[r][c4+3]=v.w;
      }
#pragma unroll
      for (int l = 0; l < 4; l++) {
        int l4 = tid + l*256;
        int gate = l4 >> 8, unit = (l4 >> 4) & 15, kq = (l4 & 15) * 4;
        float4 v = *(const float4*)(g_Wcat + (size_t)(gate*512 + u0 + unit)*1024 + kc + kq);
        wsl[gate][kq+0][unit]=v.x; wsl[gate][kq+1][unit]=v.y;
        wsl[gate][kq+2][unit]=v.z; wsl[gate][kq+3][unit]=v.w;
      }
      __syncthreads();
#pragma unroll 8
      for (int k=0;k<64;k++){
        float xv = xs[tb][k];
        a0 = fmaf(xv, wsl[0][k][tu], a0);
        a1 = fmaf(xv, wsl[1][k][tu], a1);
        a2 = fmaf(xv, wsl[2][k][tu], a2);
        a3 = fmaf(xv, wsl[3][k][tu], a3);
      }
      __syncthreads();
    }
    {
      const int b = b0 + tb, u = u0 + tu;
      const float* tp = g_tokpre + ((size_t)s*64 + b)*2048;
      float zi = a0 + tp[u];
      float zf = a1 + tp[512 + u];
      float zg = a2 + tp[1024 + u];
      float zo = a3 + tp[1536 + u];
      c_reg = sigf(zf)*c_reg + sigf(zi)*tanhf(zg);
      dx_out[b*1024 + 512 + u] = sigf(zo)*tanhf(c_reg);
    }
    __threadfence();
    gbar(bar, 128u*(unsigned)(2*s+1));

    // ---- attention + context + logits + log_softmax (blocks 0..63) ----
    if (bid < 64) {
      const int b = bid;
      float* dxb = dx_out + b*1024;
      sh[tid]       = __ldcg(&dxb[512 + tid]);
      sh[tid + 256] = __ldcg(&dxb[768 + tid]);
      __syncthreads();

      // q = relu(h @ phi_W^T + phi_b)
      {
        int m = tid & 127, half = tid >> 7;
        const float* w = phi_W + (size_t)m*512 + half*256;
        float acc = 0.f;
        for (int k=0;k<256;k+=4){
          float4 hv = *(float4*)&sh[half*256 + k];
          float4 wv = *(const float4*)&w[k];
          acc += hv.x*wv.x + hv.y*wv.y + hv.z*wv.z + hv.w*wv.w;
        }
        if (half == 0) sq[m] = acc;
        __syncthreads();
        if (half == 1) sq[m] = fmaxf(sq[m] + acc + phi_b[m], 0.f);
        __syncthreads();
      }

      // scores + softmax over t
      {
        const float* cfp = g_cf + ((size_t)b*256 + tid)*128;
        float sc = 0.f;
        for (int m=0;m<128;m+=4){
          float4 qv = *(float4*)&sq[m];
          float4 cv = *(const float4*)&cfp[m];
          sc += qv.x*cv.x + qv.y*cv.y + qv.z*cv.z + qv.w*cv.w;
        }
        float mx = sc;
        for (int o=16;o;o>>=1) mx = fmaxf(mx, __shfl_xor_sync(~0u, mx, o));
        if ((tid & 31) == 0) sred[tid>>5] = mx;
        __syncthreads();
        float bm = sred[0];
#pragma unroll
        for (int i=1;i<8;i++) bm = fmaxf(bm, sred[i]);
        float e = expf(sc - bm);
        float sm = e;
        for (int o=16;o;o>>=1) sm += __shfl_xor_sync(~0u, sm, o);
        __syncthreads();
        if ((tid & 31) == 0) sred[tid>>5] = sm;
        __syncthreads();
        float ts = 0.f;
#pragma unroll
        for (int i=0;i<8;i++) ts += sred[i];
        satt[tid] = e / ts;
        __syncthreads();
      }

      // ctx = att @ feats[b]
      {
        const float* fb = g_feats + (size_t)b*256*512;
        float a4=0.f, a5=0.f;
        for (int t=0;t<256;t++){
          float at = satt[t];
          const float* fr = fb + (size_t)t*512;
          a4 = fmaf(at, fr[tid],       a4);
          a5 = fmaf(at, fr[tid + 256], a5);
        }
        sctx[tid] = a4; sctx[tid+256] = a5;
        dxb[tid] = a4;  dxb[tid+256] = a5;
        __syncthreads();
      }

      // logits + log_softmax
      if (tid < 48) {
        const float* w = fc_W + (size_t)tid*1024;
        float acc = fc_b[tid];
        for (int k=0;k<512;k+=4){
          float4 hv = *(float4*)&sh[k];
          float4 w1 = *(const float4*)&w[k];
          acc += hv.x*w1.x + hv.y*w1.y + hv.z*w1.z + hv.w*w1.w;
          float4 cv = *(float4*)&sctx[k];
          float4 w2 = *(const float4*)&w[512 + k];
          acc += cv.x*w2.x + cv.y*w2.y + cv.z*w2.z + cv.w*w2.w;
        }
        slog[tid] = acc;
      }
      __syncthreads();
      if (tid == 0) {
        float mx = slog[0];
        for (int i=1;i<48;i++) mx = fmaxf(mx, slog[i]);
        float sm = 0.f;
        for (int i=0;i<48;i++) sm += expf(slog[i] - mx);
        sred[0] = mx + logf(sm);
      }
      __syncthreads();
      if (tid < 48) out[((size_t)b*150 + s)*48 + tid] = slog[tid] - sred[0];
      __syncthreads();
    }
    __threadfence();
    gbar(bar, 128u*(unsigned)(2*s+2));
  }
}

// ---------------- small prep/util kernels ----------------
__global__ void zero_bar_k(){
  if (threadIdx.x < 8) g_bar[threadIdx.x] = 0u;
}
__global__ void prep_wcat_k(const float* __restrict__ s_Wih, const float* __restrict__ s_Whh){
  size_t i = (size_t)blockIdx.x*256 + threadIdx.x;     // 2048*1024
  int j = (int)(i & 1023), g = (int)(i >> 10);
  g_Wcat[i] = (j < 512) ? s_Wih[(size_t)g*560 + 48 + j]
                        : s_Whh[(size_t)g*512 + j - 512];
}
__global__ void prep_tok_k(const int* __restrict__ gt,
                           const float* __restrict__ s_Wih,
                           const float* __restrict__ s_b){
  size_t i = (size_t)blockIdx.x*256 + threadIdx.x;     // 150*64*2048
  int g = (int)(i & 2047);
  int sb = (int)(i >> 11);
  int b = sb & 63, s = sb >> 6;
  int tok = (s == 0) ? 0 : gt[b*150 + s - 1];
  g_tokpre[i] = s_b[g] + s_Wih[(size_t)g*560 + tok];
}
__global__ void dec_init_k(){
  int i = blockIdx.x*256 + threadIdx.x;                // 64*1024
  int b = i >> 10, j = i & 1023;
  g_dxA[i] = (j < 512) ? g_feats[(size_t)b*256*512 + j] : 0.f;
}
__global__ void write_hc_k(float* __restrict__ out){
  int i = blockIdx.x*256 + threadIdx.x;                // 64*1024
  int b = i >> 10, j = i & 1023;
  int dir = (j >> 8) & 1, u = j & 255;
  float v = (j < 512) ? g_hA[dir*16384 + b*256 + u]
                      : g_c [dir*16384 + b*256 + u];
  out[i] = v;
}

// ---------------- launch ----------------
extern "C" void kernel_launch(void* const* d_in, const int* in_sizes, int n_in,
                              void* d_out, int out_size)
{
  (void)in_sizes; (void)n_in; (void)out_size;
  const float* inputs = (const float*)d_in[0];
  const int*   gt     = (const int*)d_in[1];
  const float* P[29];
  for (int i=2;i<29;i++) P[i] = (const float*)d_in[i];
  float* out = (float*)d_out;

  float *pre, *buf0, *buf1, *feats, *cfb;
  unsigned* dbar;
  cudaGetSymbolAddress((void**)&pre,   g_pre);
  cudaGetSymbolAddress((void**)&buf0,  g_buf0);
  cudaGetSymbolAddress((void**)&buf1,  g_buf1);
  cudaGetSymbolAddress((void**)&feats, g_feats);
  cudaGetSymbolAddress((void**)&cfb,   g_cf);
  cudaGetSymbolAddress((void**)&dbar,  g_bar);

  const int ENC_SMEM = (256*64 + 16*256 + 64*17) * 4;   // 86272 B
  static int attr_set = 0;
  if (!attr_set) {
    cudaFuncSetAttribute(enc_scan_k, cudaFuncAttributeMaxDynamicSharedMemorySize, ENC_SMEM);
    attr_set = 1;
  }

  zero_bar_k<<<1, 32>>>();

  // ---- encoder: 3 pyramid biLSTM layers ----
  const float* Xs[3] = { inputs, buf0, buf1 };
  float*       Os[3] = { buf0, buf1, feats };
  const int    Ks[3] = { 160, 1024, 1024 };
  const int    Ts[3] = { 1024, 512, 256 };

  for (int l = 0; l < 3; l++) {
    const int base = 2 + l*6;
    const int M = 64 * Ts[l];
    sgemm_k<<<dim3(8, M/128), 256>>>(Xs[l], P[base+0], P[base+2], pre,        Ks[l], 2048, 0);
    sgemm_k<<<dim3(8, M/128), 256>>>(Xs[l], P[base+3], P[base+5], pre + 1024, Ks[l], 2048, 0);
    enc_scan_k<<<dim3(16,4,2), 256, ENC_SMEM>>>(P[base+1], P[base+4], Os[l], Ts[l], dbar + l);
  }

  // ---- comp_feat = relu(feats @ psi_W^T + psi_b) ----
  sgemm_k<<<dim3(1, 128), 256>>>(feats, P[25], P[26], cfb, 512, 128, 1);

  // ---- decoder prep ----
  prep_wcat_k<<<8192, 256>>>(P[20], P[21]);
  prep_tok_k<<<76800, 256>>>(gt, P[20], P[22]);
  dec_init_k<<<256, 256>>>();

  // ---- decoder (persistent, all 150 steps) ----
  dec_scan_k<<<128, 256>>>(P[23], P[24], P[27], P[28], out, dbar + 3);

  // ---- listener_hc ----
  write_hc_k<<<256, 256>>>(out + (size_t)64*150*48);
}